// round 1
// baseline (speedup 1.0000x reference)
#include <cuda_runtime.h>
#include <cuda_bf16.h>
#include <cstddef>

#define NN 50000
#define EE 600000
#define GG 512
#define MM 2048
#define DD 128
#define FFN 256
#define LL 3
#define BN_EPS 1e-5f

// ---------------- scratch (device globals; no allocation allowed) ----------------
__device__ float g_bufA[NN * DD];
__device__ float g_bufB[NN * DD];
__device__ float g_bufC[NN * DD];
__device__ float g_norm_src[NN];
__device__ float g_norm_dst[NN];
__device__ float g_stats[2 * DD];
__device__ float g_gsum[GG * DD];
__device__ float g_gcnt[GG];
__device__ float g_msum[(MM + 1) * DD];
__device__ float g_mcnt[MM + 1];
__device__ float g_headin[(GG + MM) * DD];
__device__ float g_head1[(GG + MM) * FFN];
__device__ float g_head2[(GG + MM) * FFN];

// ---------------- degree / norm ----------------
__global__ void k_degrees(const int* __restrict__ src, const int* __restrict__ dst) {
    int e = blockIdx.x * blockDim.x + threadIdx.x;
    if (e < EE) {
        atomicAdd(&g_norm_src[src[e]], 1.0f);
        atomicAdd(&g_norm_dst[dst[e]], 1.0f);
    }
}

__global__ void k_norms() {
    int i = blockIdx.x * blockDim.x + threadIdx.x;
    if (i < NN) {
        g_norm_src[i] = rsqrtf(fmaxf(g_norm_src[i], 1.0f));
        g_norm_dst[i] = rsqrtf(fmaxf(g_norm_dst[i], 1.0f));
    }
}

// ---------------- tiled GEMM: Y = act( (X .* rowscale) @ W + bias ) ----------------
// 64-row tile x 128-col tile per block (blockIdx.y tiles columns), K chunked by 128.
__global__ void k_gemm(const float* __restrict__ X, const float* __restrict__ W,
                       const float* __restrict__ bias, const float* __restrict__ rowscale,
                       float* __restrict__ Y, int nrows, int K, int ncols, int do_relu) {
    extern __shared__ float sm[];
    float* Ws = sm;               // 128*128
    float* Xs = sm + 128 * 128;   // 64*128
    const int tid = threadIdx.x;
    const int tx = tid & 31;      // 32 col-groups of 4 cols
    const int ty = tid >> 5;      // 8 row-groups of 8 rows
    const int r0 = blockIdx.x * 64;
    const int c0 = blockIdx.y * 128;

    float4 acc[8];
#pragma unroll
    for (int m = 0; m < 8; m++) acc[m] = make_float4(0.f, 0.f, 0.f, 0.f);

    for (int kb = 0; kb < K; kb += 128) {
#pragma unroll
        for (int i = 0; i < 16; i++) {
            int f = tid + 256 * i;          // 4096 float4 of W tile
            int r = f >> 5, c4 = f & 31;
            ((float4*)Ws)[f] = *(const float4*)&W[(size_t)(kb + r) * ncols + c0 + c4 * 4];
        }
#pragma unroll
        for (int i = 0; i < 8; i++) {
            int f = tid + 256 * i;          // 2048 float4 of X tile
            int m = f >> 5, k4 = f & 31;
            int row = r0 + m;
            float4 v = make_float4(0.f, 0.f, 0.f, 0.f);
            if (row < nrows) {
                v = *(const float4*)&X[(size_t)row * K + kb + k4 * 4];
                if (rowscale) {
                    float s = rowscale[row];
                    v.x *= s; v.y *= s; v.z *= s; v.w *= s;
                }
            }
            ((float4*)Xs)[f] = v;
        }
        __syncthreads();

#pragma unroll 2
        for (int k = 0; k < 128; k += 4) {
            float4 xv[8];
#pragma unroll
            for (int m = 0; m < 8; m++)
                xv[m] = *(const float4*)&Xs[(ty * 8 + m) * 128 + k];
#pragma unroll
            for (int kk = 0; kk < 4; kk++) {
                float4 w = *(const float4*)&Ws[(k + kk) * 128 + tx * 4];
#pragma unroll
                for (int m = 0; m < 8; m++) {
                    float xvv = (kk == 0) ? xv[m].x : (kk == 1) ? xv[m].y
                              : (kk == 2) ? xv[m].z : xv[m].w;
                    acc[m].x = fmaf(xvv, w.x, acc[m].x);
                    acc[m].y = fmaf(xvv, w.y, acc[m].y);
                    acc[m].z = fmaf(xvv, w.z, acc[m].z);
                    acc[m].w = fmaf(xvv, w.w, acc[m].w);
                }
            }
        }
        __syncthreads();
    }

    float4 b4 = make_float4(0.f, 0.f, 0.f, 0.f);
    if (bias) b4 = *(const float4*)&bias[c0 + tx * 4];
#pragma unroll
    for (int m = 0; m < 8; m++) {
        int row = r0 + ty * 8 + m;
        if (row < nrows) {
            float4 o;
            o.x = acc[m].x + b4.x; o.y = acc[m].y + b4.y;
            o.z = acc[m].z + b4.z; o.w = acc[m].w + b4.w;
            if (do_relu) {
                o.x = fmaxf(o.x, 0.f); o.y = fmaxf(o.y, 0.f);
                o.z = fmaxf(o.z, 0.f); o.w = fmaxf(o.w, 0.f);
            }
            *(float4*)&Y[(size_t)row * ncols + c0 + tx * 4] = o;
        }
    }
}

// ---------------- edge scatter: C[dst] += B[src]  (warp per edge, float4 red) ----------------
__global__ void k_scatter(const int* __restrict__ src, const int* __restrict__ dst) {
    int g = blockIdx.x * blockDim.x + threadIdx.x;
    int e = g >> 5;
    int lane = threadIdx.x & 31;
    if (e >= EE) return;
    int s = src[e], d = dst[e];
    float4 v = ((const float4*)(g_bufB + (size_t)s * DD))[lane];
    atomicAdd(((float4*)(g_bufC + (size_t)d * DD)) + lane, v);
}

// ---------------- y = relu(C*norm_dst + bg) + B  -> A ----------------
__global__ void k_combine(const float* __restrict__ bg) {
    int idx = blockIdx.x * blockDim.x + threadIdx.x;  // N*32 float4s
    if (idx >= NN * 32) return;
    int row = idx >> 5, j4 = idx & 31;
    float nd = g_norm_dst[row];
    float4 c = ((const float4*)g_bufC)[idx];
    float4 b4 = ((const float4*)bg)[j4];
    float4 r = ((const float4*)g_bufB)[idx];
    float4 o;
    o.x = fmaxf(fmaf(c.x, nd, b4.x), 0.f) + r.x;
    o.y = fmaxf(fmaf(c.y, nd, b4.y), 0.f) + r.y;
    o.z = fmaxf(fmaf(c.z, nd, b4.z), 0.f) + r.z;
    o.w = fmaxf(fmaf(c.w, nd, b4.w), 0.f) + r.w;
    ((float4*)g_bufA)[idx] = o;
}

// ---------------- BatchNorm ----------------
__global__ void k_bn_stats() {
    int j = threadIdx.x;  // 128 threads, one column each
    float s = 0.f, sq = 0.f;
    for (int r = blockIdx.x; r < NN; r += gridDim.x) {
        float v = g_bufA[(size_t)r * DD + j];
        s += v; sq += v * v;
    }
    atomicAdd(&g_stats[j], s);
    atomicAdd(&g_stats[DD + j], sq);
}

__global__ void k_bn_norm(const float* __restrict__ gamma, const float* __restrict__ beta) {
    int idx = blockIdx.x * blockDim.x + threadIdx.x;  // N*32 float4s
    if (idx >= NN * 32) return;
    int j4 = idx & 31;
    float4 sum = ((const float4*)g_stats)[j4];
    float4 sq  = ((const float4*)g_stats)[32 + j4];
    float4 ga  = ((const float4*)gamma)[j4];
    float4 be  = ((const float4*)beta)[j4];
    const float invN = 1.0f / (float)NN;
    float4 mu, iv;
    mu.x = sum.x * invN; mu.y = sum.y * invN; mu.z = sum.z * invN; mu.w = sum.w * invN;
    iv.x = rsqrtf(fmaxf(sq.x * invN - mu.x * mu.x, 0.f) + BN_EPS);
    iv.y = rsqrtf(fmaxf(sq.y * invN - mu.y * mu.y, 0.f) + BN_EPS);
    iv.z = rsqrtf(fmaxf(sq.z * invN - mu.z * mu.z, 0.f) + BN_EPS);
    iv.w = rsqrtf(fmaxf(sq.w * invN - mu.w * mu.w, 0.f) + BN_EPS);
    float4 v = ((const float4*)g_bufA)[idx];
    float4 o;
    o.x = (v.x - mu.x) * iv.x * ga.x + be.x;
    o.y = (v.y - mu.y) * iv.y * ga.y + be.y;
    o.z = (v.z - mu.z) * iv.z * ga.z + be.z;
    o.w = (v.w - mu.w) * iv.w * ga.w + be.w;
    ((float4*)g_bufA)[idx] = o;
}

// ---------------- pooling ----------------
__global__ void k_pool(const int* __restrict__ gid, const int* __restrict__ mid) {
    int g = blockIdx.x * blockDim.x + threadIdx.x;
    int node = g >> 5;
    int lane = threadIdx.x & 31;
    if (node >= NN) return;
    float4 v = ((const float4*)(g_bufA + (size_t)node * DD))[lane];
    atomicAdd(((float4*)(g_gsum + (size_t)gid[node] * DD)) + lane, v);
    atomicAdd(((float4*)(g_msum + (size_t)mid[node] * DD)) + lane, v);
}

__global__ void k_counts(const int* __restrict__ gid, const int* __restrict__ mid) {
    int i = blockIdx.x * blockDim.x + threadIdx.x;
    if (i < NN) {
        atomicAdd(&g_gcnt[gid[i]], 1.0f);
        atomicAdd(&g_mcnt[mid[i]], 1.0f);
    }
}

__global__ void k_finalize(float* __restrict__ out_gf) {
    int idx = blockIdx.x * blockDim.x + threadIdx.x;  // (G+M)*D
    if (idx >= (GG + MM) * DD) return;
    int row = idx / DD, j = idx % DD;
    float v;
    if (row < GG) {
        v = g_gsum[row * DD + j] / fmaxf(g_gcnt[row], 1.0f);
        out_gf[row * DD + j] = v;
    } else {
        int mrow = row - GG + 1;  // drop motif segment 0
        v = g_msum[mrow * DD + j] / fmaxf(g_mcnt[mrow], 1.0f);
    }
    g_headin[idx] = v;
}

// ---------------- launch ----------------
extern "C" void kernel_launch(void* const* d_in, const int* in_sizes, int n_in,
                              void* d_out, int out_size) {
    const float* node_feats = (const float*)d_in[0];
    const int*   src        = (const int*)d_in[1];
    const int*   dst        = (const int*)d_in[2];
    const int*   gid        = (const int*)d_in[3];
    const int*   mid        = (const int*)d_in[4];
    const float* Wg         = (const float*)d_in[5];
    const float* bg         = (const float*)d_in[6];
    const float* Wr         = (const float*)d_in[7];
    const float* br         = (const float*)d_in[8];
    const float* gamma      = (const float*)d_in[9];
    const float* beta       = (const float*)d_in[10];
    const float* W_feat     = (const float*)d_in[11];
    const float* b_feat     = (const float*)d_in[12];
    const float* W1         = (const float*)d_in[13];
    const float* b1         = (const float*)d_in[14];
    const float* W2         = (const float*)d_in[15];
    const float* b2         = (const float*)d_in[16];
    float* out = (float*)d_out;

    void *pA, *pB, *pC, *pns, *pnd, *pstats, *pgsum, *pgcnt, *pmsum, *pmcnt, *phin, *ph1, *ph2;
    cudaGetSymbolAddress(&pA, g_bufA);
    cudaGetSymbolAddress(&pB, g_bufB);
    cudaGetSymbolAddress(&pC, g_bufC);
    cudaGetSymbolAddress(&pns, g_norm_src);
    cudaGetSymbolAddress(&pnd, g_norm_dst);
    cudaGetSymbolAddress(&pstats, g_stats);
    cudaGetSymbolAddress(&pgsum, g_gsum);
    cudaGetSymbolAddress(&pgcnt, g_gcnt);
    cudaGetSymbolAddress(&pmsum, g_msum);
    cudaGetSymbolAddress(&pmcnt, g_mcnt);
    cudaGetSymbolAddress(&phin, g_headin);
    cudaGetSymbolAddress(&ph1, g_head1);
    cudaGetSymbolAddress(&ph2, g_head2);

    const int SMEM = (128 * 128 + 64 * 128) * 4;  // 96 KB dynamic shared
    cudaFuncSetAttribute(k_gemm, cudaFuncAttributeMaxDynamicSharedMemorySize, SMEM);

    // degrees -> norms
    cudaMemsetAsync(pns, 0, NN * sizeof(float));
    cudaMemsetAsync(pnd, 0, NN * sizeof(float));
    k_degrees<<<(EE + 255) / 256, 256>>>(src, dst);
    k_norms<<<(NN + 255) / 256, 256>>>();

    const int gemm_blocks = (NN + 63) / 64;           // 782
    const int elw_blocks = (NN * 32 + 255) / 256;     // 6250
    const int scat_blocks = (EE * 32 + 255) / 256;    // 75000

    for (int l = 0; l < LL; l++) {
        const float* hin = (l == 0) ? node_feats : (const float*)pA;

        // hw = (h * norm_src) @ Wg[l] -> B
        k_gemm<<<dim3(gemm_blocks, 1), 256, SMEM>>>(
            hin, Wg + (size_t)l * DD * DD, nullptr, (const float*)pns,
            (float*)pB, NN, DD, DD, 0);

        // agg: C = 0; C[dst] += B[src]
        cudaMemsetAsync(pC, 0, (size_t)NN * DD * sizeof(float));
        k_scatter<<<scat_blocks, 256>>>(src, dst);

        // res = relu(h @ Wr[l] + br[l]) -> B (previous B consumed by scatter)
        k_gemm<<<dim3(gemm_blocks, 1), 256, SMEM>>>(
            hin, Wr + (size_t)l * DD * DD, br + (size_t)l * DD, nullptr,
            (float*)pB, NN, DD, DD, 1);

        // y = relu(C*norm_dst + bg) + B -> A
        k_combine<<<elw_blocks, 256>>>(bg + (size_t)l * DD);

        // BatchNorm (training stats, biased var)
        cudaMemsetAsync(pstats, 0, 2 * DD * sizeof(float));
        k_bn_stats<<<512, 128>>>();
        k_bn_norm<<<elw_blocks, 256>>>(gamma + (size_t)l * DD, beta + (size_t)l * DD);
    }

    // pooling
    cudaMemsetAsync(pgsum, 0, (size_t)GG * DD * sizeof(float));
    cudaMemsetAsync(pgcnt, 0, GG * sizeof(float));
    cudaMemsetAsync(pmsum, 0, (size_t)(MM + 1) * DD * sizeof(float));
    cudaMemsetAsync(pmcnt, 0, (MM + 1) * sizeof(float));
    k_pool<<<(NN * 32 + 255) / 256, 256>>>(gid, mid);
    k_counts<<<(NN + 255) / 256, 256>>>(gid, mid);
    k_finalize<<<((GG + MM) * DD + 255) / 256, 256>>>(out);

    // head MLP on combined [graph_feats ; h_sub] = 2560 rows,
    // final GEMM writes out_global||out_sub contiguously into d_out.
    const int HR = GG + MM;              // 2560
    const int hblocks = (HR + 63) / 64;  // 40
    k_gemm<<<dim3(hblocks, FFN / 128), 256, SMEM>>>(
        (const float*)phin, W_feat, b_feat, nullptr, (float*)ph1, HR, DD, FFN, 0);
    k_gemm<<<dim3(hblocks, FFN / 128), 256, SMEM>>>(
        (const float*)ph1, W1, b1, nullptr, (float*)ph2, HR, FFN, FFN, 1);
    k_gemm<<<dim3(hblocks, 1), 256, SMEM>>>(
        (const float*)ph2, W2, b2, nullptr, out + (size_t)GG * DD, HR, FFN, DD, 0);
}